// round 16
// baseline (speedup 1.0000x reference)
#include <cuda_runtime.h>
#include <cuda_fp16.h>
#include <math.h>

// Fused CNN + analytic quantum circuit. One CTA per FOUR images, 416 threads
// (13 warps), 2 CTAs/SM. conv2 on TENSOR CORES: 9 tap-GEMMs via
// mma.sync.m16n8k16, fp16 hi/lo split (3 MMAs) for fp32-level accuracy.
// Warp computes m-tiles {wid, wid+13} interleaved; B fragments read as uint4
// (layout [tap][lane][nt][w], one tap = 64 uint4) and reused for both tiles.
// C pitch 34 kills the 128B-stride epilogue bank conflicts.
//
// Quantum part collapses analytically:
//   P_i(1) = (1 + sin f_i)/2
//   <Z_j>  = - sum_{b in {0,1}^4} prod_i P_i(b_i) * sin( sum_{i: b_i=1} w[i][j] )
//   out_j  = sigmoid(10 * <Z_j>)

#define LDSM4(r0, r1, r2, r3, addr) \
    asm volatile("ldmatrix.sync.aligned.m8n8.x4.shared.b16 {%0,%1,%2,%3}, [%4];" \
        : "=r"(r0), "=r"(r1), "=r"(r2), "=r"(r3) : "r"(addr))

#define MMA16816(c, a0, a1, a2, a3, b0, b1) \
    asm volatile("mma.sync.aligned.m16n8k16.row.col.f32.f16.f16.f32 " \
        "{%0,%1,%2,%3}, {%4,%5,%6,%7}, {%8,%9}, {%0,%1,%2,%3};" \
        : "+f"(c[0]), "+f"(c[1]), "+f"(c[2]), "+f"(c[3]) \
        : "r"(a0), "r"(a1), "r"(a2), "r"(a3), "r"(b0), "r"(b1))

__device__ __forceinline__ unsigned pack_h2(__half a, __half b) {
    return (unsigned)__half_as_ushort(a) | ((unsigned)__half_as_ushort(b) << 16);
}

#define CPITCH 34           // C row pitch in floats (kills 128B-stride bank conflicts)

// shared-memory layout (float units); all blocks 16B-aligned
// UNION region (floats 3200..17792): act_hi/act_lo/bf during MMA, then C after barrier.
#define OFF_IMG    0        // [3200] phase A: 4 images [3136]; phase E: s_p2 [4][800]
#define OFF_ACT_HI 3200     // half[9984] = [4][12][12][16] + zero-pad
#define OFF_ACT_LO 8192     // half[9984]
#define OFF_BF_HI  13184    // u32[2304] B fragments hi: [tap][lane][nt][w]
#define OFF_BF_LO  15488    // u32[2304]
#define OFF_C      3200     // [416*34=14144] C f32, pitch 34 (aliases act+bf)
#define OFF_W1     17792    // [144]
#define OFF_B1     17936    // [16]
#define OFF_B2     17952    // [32]
#define OFF_FEAT   17984    // [16]
#define SM_FLOATS  18000
#define SM_BYTES   (SM_FLOATS * 4)

#define NT 416              // 13 warps

__global__ __launch_bounds__(NT, 2)
void hybrid_kernel(const float* __restrict__ x,
                   const float* __restrict__ w1g, const float* __restrict__ b1g,
                   const float* __restrict__ w2g, const float* __restrict__ b2g,
                   const float* __restrict__ dwg, const float* __restrict__ dbg,
                   const float* __restrict__ qwg,
                   float* __restrict__ out, int B)
{
    extern __shared__ __align__(16) float sm[];
    float*    s_img    = sm + OFF_IMG;   // phase A
    float*    s_p2     = sm + OFF_IMG;   // phase E (images dead after conv1)
    float*    s_C      = sm + OFF_C;     // post-MMA (act/bf dead)
    __half*   s_act_hi = (__half*)(sm + OFF_ACT_HI);
    __half*   s_act_lo = (__half*)(sm + OFF_ACT_LO);
    unsigned* s_bf_hi  = (unsigned*)(sm + OFF_BF_HI);
    unsigned* s_bf_lo  = (unsigned*)(sm + OFF_BF_LO);
    float*    s_w1     = sm + OFF_W1;
    float*    s_b1     = sm + OFF_B1;
    float*    s_b2     = sm + OFF_B2;
    float*    s_feat   = sm + OFF_FEAT;

    const int tid  = threadIdx.x;
    const int img0 = blockIdx.x * 4;
    const int nimg = min(4, B - img0);

    // ---------------- load phase ----------------
    {
        const float* xin = x + img0 * 784;
        const int cnt = nimg * 784;
        for (int i = tid; i < cnt; i += NT) s_img[i] = xin[i];
    }
    // conv2 weight fragments (hi/lo), layout [tap][lane][nt][w]:
    // per lane the 8 u32 (4 nt x 2 w) are CONSECUTIVE -> 2x LDS.128 per tap.
    // idx = tap*256 + lane*8 + nt*2 + w; halves (k,n),(k+1,n),
    // k=(lane&3)*2+8w, n=nt*8+lane/4.
    for (int idx = tid; idx < 2304; idx += NT) {
        const int w    = idx & 1;
        const int nt   = (idx >> 1) & 3;
        const int ln   = (idx >> 3) & 31;
        const int tap  = idx >> 8;
        const int k    = (ln & 3) * 2 + 8 * w;
        const int n    = nt * 8 + (ln >> 2);
        const float v0 = w2g[tap * 512 + k * 32 + n];
        const float v1 = w2g[tap * 512 + (k + 1) * 32 + n];
        const __half h0 = __float2half_rn(v0), h1 = __float2half_rn(v1);
        const __half l0 = __float2half_rn(v0 - __half2float(h0));
        const __half l1 = __float2half_rn(v1 - __half2float(h1));
        s_bf_hi[idx] = pack_h2(h0, h1);
        s_bf_lo[idx] = pack_h2(l0, l1);
    }
    // zero the pad rows (positions >= 400)
    {
        unsigned* zh = (unsigned*)(s_act_hi + 9216);
        unsigned* zl = (unsigned*)(s_act_lo + 9216);
        for (int i = tid; i < 384; i += NT) { zh[i] = 0u; zl[i] = 0u; }
    }
    for (int i = tid; i < 144; i += NT) s_w1[i] = w1g[i];
    if (tid < 16) s_b1[tid] = b1g[tid];
    if (tid < 32) s_b2[tid] = b2g[tid];
    if (tid < 16) s_feat[tid] = dbg[tid & 3];
    __syncthreads();

    // ---------------- conv1 (3x3x1x16) + relu + 2x2 maxpool -> s_act hi/lo ---------
    for (int u = tid; u < nimg * 384; u += NT) {
        const int im   = u / 384;
        const int rem  = u - im * 384;
        const int half = rem & 1;
        const int idx  = rem >> 1;
        const int co   = idx & 15;
        const int py   = idx >> 4;          // 0..11
        float w[9];
        #pragma unroll
        for (int k = 0; k < 9; k++) w[k] = s_w1[k * 16 + co];
        const float bias = s_b1[co];
        const float* in0 = s_img + im * 784 + (2 * py) * 28;
        const int px0 = half * 6;

        float win[4][4];
        #pragma unroll
        for (int r = 0; r < 4; r++) {
            const float2 v = *(const float2*)(in0 + r * 28 + 2 * px0);
            win[r][2] = v.x; win[r][3] = v.y;
        }
        #pragma unroll
        for (int dpx = 0; dpx < 6; dpx++) {
            const int px = px0 + dpx;
            #pragma unroll
            for (int r = 0; r < 4; r++) {
                win[r][0] = win[r][2];
                win[r][1] = win[r][3];
                const float2 v = *(const float2*)(in0 + r * 28 + 2 * px + 2);
                win[r][2] = v.x; win[r][3] = v.y;
            }
            float best = -1e30f;
            #pragma unroll
            for (int dy = 0; dy < 2; dy++) {
                #pragma unroll
                for (int dx = 0; dx < 2; dx++) {
                    float acc = bias;
                    #pragma unroll
                    for (int ky = 0; ky < 3; ky++) {
                        #pragma unroll
                        for (int kx = 0; kx < 3; kx++)
                            acc += win[dy + ky][dx + kx] * w[ky * 3 + kx];
                    }
                    best = fmaxf(best, acc);
                }
            }
            const float v = fmaxf(best, 0.0f);
            const __half h = __float2half_rn(v);
            const __half l = __float2half_rn(v - __half2float(h));
            const int ei = im * 2304 + (py * 12 + px) * 16 + co;
            s_act_hi[ei] = h;
            s_act_lo[ei] = l;
        }
    }
    __syncthreads();

    // ---------------- conv2 on tensor cores: C = sum_tap A_tap * W_tap -------------
    // warp owns m-tiles {wid, wid+13}, interleaved; B fragments loaded once/tap.
    {
        const int wid  = tid >> 5;
        const int lane = tid & 31;
        const int m    = lane & 15;
        const int koff = (lane >> 4) * 8;
        const unsigned hi_base = (unsigned)__cvta_generic_to_shared(s_act_hi);
        const unsigned lo_base = (unsigned)__cvta_generic_to_shared(s_act_lo);
        // one tap block = 256 u32 = 64 uint4; lane's 8 u32 start at uint4 lane*2
        const uint4* bfh_lane = (const uint4*)(s_bf_hi) + lane * 2;
        const uint4* bfl_lane = (const uint4*)(s_bf_lo) + lane * 2;

        unsigned ahb[2], alb[2];
        #pragma unroll
        for (int t = 0; t < 2; t++) {
            const int p = (wid + t * 13) * 16 + m;
            int row_elems;
            if (p < 400) {
                const int imq = p / 100;
                const int rq  = p - imq * 100;
                row_elems = imq * 2304 + (rq / 10) * 192 + (rq % 10) * 16;
            } else {
                row_elems = 9216;              // zeroed pad row (result discarded)
            }
            ahb[t] = hi_base + (unsigned)(row_elems + koff) * 2u;
            alb[t] = lo_base + (unsigned)(row_elems + koff) * 2u;
        }

        float acc[2][4][4];
        #pragma unroll
        for (int t = 0; t < 2; t++)
            #pragma unroll
            for (int nt = 0; nt < 4; nt++)
                #pragma unroll
                for (int c = 0; c < 4; c++) acc[t][nt][c] = 0.0f;

        #pragma unroll
        for (int tap = 0; tap < 9; tap++) {
            const unsigned toff = (unsigned)(((tap / 3) * 12 + (tap % 3)) * 32);
            unsigned ah[2][4], al[2][4];
            #pragma unroll
            for (int t = 0; t < 2; t++) {
                LDSM4(ah[t][0], ah[t][1], ah[t][2], ah[t][3], ahb[t] + toff);
                LDSM4(al[t][0], al[t][1], al[t][2], al[t][3], alb[t] + toff);
            }
            const uint4 h01 = bfh_lane[tap * 64];       // nt0,nt1 (tap block = 64 uint4)
            const uint4 h23 = bfh_lane[tap * 64 + 1];   // nt2,nt3
            const uint4 l01 = bfl_lane[tap * 64];
            const uint4 l23 = bfl_lane[tap * 64 + 1];
            #pragma unroll
            for (int t = 0; t < 2; t++) {
                MMA16816(acc[t][0], ah[t][0], ah[t][1], ah[t][2], ah[t][3], h01.x, h01.y);
                MMA16816(acc[t][0], al[t][0], al[t][1], al[t][2], al[t][3], h01.x, h01.y);
                MMA16816(acc[t][0], ah[t][0], ah[t][1], ah[t][2], ah[t][3], l01.x, l01.y);
                MMA16816(acc[t][1], ah[t][0], ah[t][1], ah[t][2], ah[t][3], h01.z, h01.w);
                MMA16816(acc[t][1], al[t][0], al[t][1], al[t][2], al[t][3], h01.z, h01.w);
                MMA16816(acc[t][1], ah[t][0], ah[t][1], ah[t][2], ah[t][3], l01.z, l01.w);
                MMA16816(acc[t][2], ah[t][0], ah[t][1], ah[t][2], ah[t][3], h23.x, h23.y);
                MMA16816(acc[t][2], al[t][0], al[t][1], al[t][2], al[t][3], h23.x, h23.y);
                MMA16816(acc[t][2], ah[t][0], ah[t][1], ah[t][2], ah[t][3], l23.x, l23.y);
                MMA16816(acc[t][3], ah[t][0], ah[t][1], ah[t][2], ah[t][3], h23.z, h23.w);
                MMA16816(acc[t][3], al[t][0], al[t][1], al[t][2], al[t][3], h23.z, h23.w);
                MMA16816(acc[t][3], ah[t][0], ah[t][1], ah[t][2], ah[t][3], l23.z, l23.w);
            }
        }
        __syncthreads();   // all act/bf reads done -> C may overwrite them

        // epilogue: fragments -> s_C[p][co], pitch 34 (conflict-free)
        const int col0 = (lane & 3) * 2;
        #pragma unroll
        for (int t = 0; t < 2; t++) {
            const int prow = (wid + t * 13) * 16 + (lane >> 2);
            #pragma unroll
            for (int nt = 0; nt < 4; nt++) {
                const int co0 = nt * 8 + col0;
                *(float2*)&s_C[prow * CPITCH + co0] =
                    make_float2(acc[t][nt][0], acc[t][nt][1]);
                *(float2*)&s_C[(prow + 8) * CPITCH + co0] =
                    make_float2(acc[t][nt][2], acc[t][nt][3]);
            }
        }
    }
    __syncthreads();

    // ---------------- bias + relu + 2x2 maxpool -> s_p2[4][800] --------------------
    for (int o = tid; o < nimg * 800; o += NT) {
        const int im  = o / 800;
        const int oo  = o - im * 800;
        const int co  = oo & 31;
        const int pos = oo >> 5;
        const int r   = pos / 5;
        const int cl  = pos - r * 5;
        const int pb  = im * 100 + (2 * r) * 10 + 2 * cl;
        const float v0 = s_C[(pb     ) * CPITCH + co];
        const float v1 = s_C[(pb +  1) * CPITCH + co];
        const float v2 = s_C[(pb + 10) * CPITCH + co];
        const float v3 = s_C[(pb + 11) * CPITCH + co];
        const float mx = fmaxf(fmaxf(v0, v1), fmaxf(v2, v3)) + s_b2[co];
        s_p2[o] = fmaxf(mx, 0.0f);
    }
    __syncthreads();

    // ---------------- dense 800 -> 4, four images ----------------------------------
    {
        float p[4][4];
        #pragma unroll
        for (int g = 0; g < 4; g++)
            #pragma unroll
            for (int c = 0; c < 4; c++) p[g][c] = 0.0f;

        for (int k = tid; k < 800; k += NT) {
            const float4 w = *(const float4*)(dwg + k * 4);
            #pragma unroll
            for (int g = 0; g < 4; g++) {
                const float v = s_p2[g * 800 + k];
                p[g][0] += v * w.x; p[g][1] += v * w.y;
                p[g][2] += v * w.z; p[g][3] += v * w.w;
            }
        }
        #pragma unroll
        for (int off = 16; off; off >>= 1) {
            #pragma unroll
            for (int g = 0; g < 4; g++)
                #pragma unroll
                for (int c = 0; c < 4; c++)
                    p[g][c] += __shfl_down_sync(0xffffffffu, p[g][c], off);
        }
        if ((tid & 31) == 0) {
            #pragma unroll
            for (int g = 0; g < 4; g++)
                #pragma unroll
                for (int c = 0; c < 4; c++)
                    atomicAdd(&s_feat[g * 4 + c], p[g][c]);
        }
    }
    __syncthreads();

    // ---------------- analytic quantum circuit + sigmoid ---------------------------
    if (tid < 16) {
        const int im = tid >> 2;
        const int j  = tid & 3;
        const int img = img0 + im;
        if (img < B) {
            float pr1[4];
            #pragma unroll
            for (int i = 0; i < 4; i++) {
                const float f = tanhf(s_feat[im * 4 + i]);
                pr1[i] = 0.5f * (1.0f + sinf(f));
            }
            float wj[4];
            #pragma unroll
            for (int i = 0; i < 4; i++) wj[i] = qwg[i * 4 + j];

            float q = 0.0f;
            #pragma unroll
            for (int b = 0; b < 16; b++) {
                float prob = 1.0f, ang = 0.0f;
                #pragma unroll
                for (int i = 0; i < 4; i++) {
                    if (b & (1 << i)) { prob *= pr1[i];        ang += wj[i]; }
                    else              { prob *= 1.0f - pr1[i]; }
                }
                q -= prob * sinf(ang);
            }
            out[img * 4 + j] = 1.0f / (1.0f + expf(-10.0f * q));
        }
    }
}

extern "C" void kernel_launch(void* const* d_in, const int* in_sizes, int n_in,
                              void* d_out, int out_size)
{
    const float* x   = (const float*)d_in[0];
    const float* w1  = (const float*)d_in[1];
    const float* b1  = (const float*)d_in[2];
    const float* w2  = (const float*)d_in[3];
    const float* b2  = (const float*)d_in[4];
    const float* dw  = (const float*)d_in[5];
    const float* db  = (const float*)d_in[6];
    const float* qw  = (const float*)d_in[7];
    float* out = (float*)d_out;

    const int B = in_sizes[0] / 784;   // NHWC 28*28*1
    static bool attr_set = false;
    if (!attr_set) {
        cudaFuncSetAttribute(hybrid_kernel,
                             cudaFuncAttributeMaxDynamicSharedMemorySize, SM_BYTES);
        attr_set = true;
    }
    hybrid_kernel<<<(B + 3) / 4, NT, SM_BYTES>>>(x, w1, b1, w2, b2, dw, db, qw, out, B);
}

// round 17
// speedup vs baseline: 1.0635x; 1.0635x over previous
#include <cuda_runtime.h>
#include <cuda_fp16.h>
#include <math.h>

// Fused CNN + analytic quantum circuit. One CTA per FOUR images, 416 threads
// (13 warps), 2 CTAs/SM. conv2 on TENSOR CORES: 9 tap-GEMMs via
// mma.sync.m16n8k16, fp16 hi/lo split (3 MMAs) for fp32-level accuracy.
// Warp computes m-tiles {wid, wid+13} interleaved; B fragments in the
// conflict-free [tap][nt][lane][w] layout (uint2 reads, 8B lane stride).
// C pitch 34 kills the 128B-stride epilogue bank conflicts.
//
// Quantum part collapses analytically:
//   P_i(1) = (1 + sin f_i)/2
//   <Z_j>  = - sum_{b in {0,1}^4} prod_i P_i(b_i) * sin( sum_{i: b_i=1} w[i][j] )
//   out_j  = sigmoid(10 * <Z_j>)

#define LDSM4(r0, r1, r2, r3, addr) \
    asm volatile("ldmatrix.sync.aligned.m8n8.x4.shared.b16 {%0,%1,%2,%3}, [%4];" \
        : "=r"(r0), "=r"(r1), "=r"(r2), "=r"(r3) : "r"(addr))

#define MMA16816(c, a0, a1, a2, a3, b0, b1) \
    asm volatile("mma.sync.aligned.m16n8k16.row.col.f32.f16.f16.f32 " \
        "{%0,%1,%2,%3}, {%4,%5,%6,%7}, {%8,%9}, {%0,%1,%2,%3};" \
        : "+f"(c[0]), "+f"(c[1]), "+f"(c[2]), "+f"(c[3]) \
        : "r"(a0), "r"(a1), "r"(a2), "r"(a3), "r"(b0), "r"(b1))

__device__ __forceinline__ unsigned pack_h2(__half a, __half b) {
    return (unsigned)__half_as_ushort(a) | ((unsigned)__half_as_ushort(b) << 16);
}

#define CPITCH 34           // C row pitch in floats (kills 128B-stride bank conflicts)

// shared-memory layout (float units); all blocks 16B-aligned
// UNION region (floats 3200..17792): act_hi/act_lo/bf during MMA, then C after barrier.
#define OFF_IMG    0        // [3200] phase A: 4 images [3136]; phase E: s_p2 [4][800]
#define OFF_ACT_HI 3200     // half[9984] = [4][12][12][16] + zero-pad
#define OFF_ACT_LO 8192     // half[9984]
#define OFF_BF_HI  13184    // u32[2304] B fragments hi: [tap][nt][lane][w]
#define OFF_BF_LO  15488    // u32[2304]
#define OFF_C      3200     // [416*34=14144] C f32, pitch 34 (aliases act+bf)
#define OFF_W1     17792    // [144]
#define OFF_B1     17936    // [16]
#define OFF_B2     17952    // [32]
#define OFF_FEAT   17984    // [16]
#define SM_FLOATS  18000
#define SM_BYTES   (SM_FLOATS * 4)

#define NT 416              // 13 warps

__global__ __launch_bounds__(NT, 2)
void hybrid_kernel(const float* __restrict__ x,
                   const float* __restrict__ w1g, const float* __restrict__ b1g,
                   const float* __restrict__ w2g, const float* __restrict__ b2g,
                   const float* __restrict__ dwg, const float* __restrict__ dbg,
                   const float* __restrict__ qwg,
                   float* __restrict__ out, int B)
{
    extern __shared__ __align__(16) float sm[];
    float*    s_img    = sm + OFF_IMG;   // phase A
    float*    s_p2     = sm + OFF_IMG;   // phase E (images dead after conv1)
    float*    s_C      = sm + OFF_C;     // post-MMA (act/bf dead)
    __half*   s_act_hi = (__half*)(sm + OFF_ACT_HI);
    __half*   s_act_lo = (__half*)(sm + OFF_ACT_LO);
    unsigned* s_bf_hi  = (unsigned*)(sm + OFF_BF_HI);
    unsigned* s_bf_lo  = (unsigned*)(sm + OFF_BF_LO);
    float*    s_w1     = sm + OFF_W1;
    float*    s_b1     = sm + OFF_B1;
    float*    s_b2     = sm + OFF_B2;
    float*    s_feat   = sm + OFF_FEAT;

    const int tid  = threadIdx.x;
    const int img0 = blockIdx.x * 4;
    const int nimg = min(4, B - img0);

    // ---------------- load phase ----------------
    {
        const float* xin = x + img0 * 784;
        const int cnt = nimg * 784;
        for (int i = tid; i < cnt; i += NT) s_img[i] = xin[i];
    }
    // conv2 weight fragments (hi/lo) in mma B-fragment layout [tap][nt][lane][w]:
    // uint2 per (tap,nt,lane) -> 8B lane stride, conflict-free.
    // halves (k,n),(k+1,n), k=(l&3)*2+8w, n=nt*8+l/4.  idx = tap*256+nt*64+l*2+w.
    for (int idx = tid; idx < 2304; idx += NT) {
        const int w    = idx & 1;
        const int ln   = (idx >> 1) & 31;
        const int nt   = (idx >> 6) & 3;
        const int tap  = idx >> 8;
        const int k    = (ln & 3) * 2 + 8 * w;
        const int n    = nt * 8 + (ln >> 2);
        const float v0 = w2g[tap * 512 + k * 32 + n];
        const float v1 = w2g[tap * 512 + (k + 1) * 32 + n];
        const __half h0 = __float2half_rn(v0), h1 = __float2half_rn(v1);
        const __half l0 = __float2half_rn(v0 - __half2float(h0));
        const __half l1 = __float2half_rn(v1 - __half2float(h1));
        s_bf_hi[idx] = pack_h2(h0, h1);
        s_bf_lo[idx] = pack_h2(l0, l1);
    }
    // zero the pad rows (positions >= 400)
    {
        unsigned* zh = (unsigned*)(s_act_hi + 9216);
        unsigned* zl = (unsigned*)(s_act_lo + 9216);
        for (int i = tid; i < 384; i += NT) { zh[i] = 0u; zl[i] = 0u; }
    }
    for (int i = tid; i < 144; i += NT) s_w1[i] = w1g[i];
    if (tid < 16) s_b1[tid] = b1g[tid];
    if (tid < 32) s_b2[tid] = b2g[tid];
    if (tid < 16) s_feat[tid] = dbg[tid & 3];
    __syncthreads();

    // ---------------- conv1 (3x3x1x16) + relu + 2x2 maxpool -> s_act hi/lo ---------
    for (int u = tid; u < nimg * 384; u += NT) {
        const int im   = u / 384;
        const int rem  = u - im * 384;
        const int half = rem & 1;
        const int idx  = rem >> 1;
        const int co   = idx & 15;
        const int py   = idx >> 4;          // 0..11
        float w[9];
        #pragma unroll
        for (int k = 0; k < 9; k++) w[k] = s_w1[k * 16 + co];
        const float bias = s_b1[co];
        const float* in0 = s_img + im * 784 + (2 * py) * 28;
        const int px0 = half * 6;

        float win[4][4];
        #pragma unroll
        for (int r = 0; r < 4; r++) {
            const float2 v = *(const float2*)(in0 + r * 28 + 2 * px0);
            win[r][2] = v.x; win[r][3] = v.y;
        }
        #pragma unroll
        for (int dpx = 0; dpx < 6; dpx++) {
            const int px = px0 + dpx;
            #pragma unroll
            for (int r = 0; r < 4; r++) {
                win[r][0] = win[r][2];
                win[r][1] = win[r][3];
                const float2 v = *(const float2*)(in0 + r * 28 + 2 * px + 2);
                win[r][2] = v.x; win[r][3] = v.y;
            }
            float best = -1e30f;
            #pragma unroll
            for (int dy = 0; dy < 2; dy++) {
                #pragma unroll
                for (int dx = 0; dx < 2; dx++) {
                    float acc = bias;
                    #pragma unroll
                    for (int ky = 0; ky < 3; ky++) {
                        #pragma unroll
                        for (int kx = 0; kx < 3; kx++)
                            acc += win[dy + ky][dx + kx] * w[ky * 3 + kx];
                    }
                    best = fmaxf(best, acc);
                }
            }
            const float v = fmaxf(best, 0.0f);
            const __half h = __float2half_rn(v);
            const __half l = __float2half_rn(v - __half2float(h));
            const int ei = im * 2304 + (py * 12 + px) * 16 + co;
            s_act_hi[ei] = h;
            s_act_lo[ei] = l;
        }
    }
    __syncthreads();

    // ---------------- conv2 on tensor cores: C = sum_tap A_tap * W_tap -------------
    // warp owns m-tiles {wid, wid+13}; B fragments loaded once per (tap,nt),
    // reused for both tiles.
    {
        const int wid  = tid >> 5;
        const int lane = tid & 31;
        const int m    = lane & 15;
        const int koff = (lane >> 4) * 8;
        const unsigned hi_base = (unsigned)__cvta_generic_to_shared(s_act_hi);
        const unsigned lo_base = (unsigned)__cvta_generic_to_shared(s_act_lo);

        unsigned ahb[2], alb[2];
        #pragma unroll
        for (int t = 0; t < 2; t++) {
            const int p = (wid + t * 13) * 16 + m;
            int row_elems;
            if (p < 400) {
                const int imq = p / 100;
                const int rq  = p - imq * 100;
                row_elems = imq * 2304 + (rq / 10) * 192 + (rq % 10) * 16;
            } else {
                row_elems = 9216;              // zeroed pad row (result discarded)
            }
            ahb[t] = hi_base + (unsigned)(row_elems + koff) * 2u;
            alb[t] = lo_base + (unsigned)(row_elems + koff) * 2u;
        }

        float acc[2][4][4];
        #pragma unroll
        for (int t = 0; t < 2; t++)
            #pragma unroll
            for (int nt = 0; nt < 4; nt++)
                #pragma unroll
                for (int c = 0; c < 4; c++) acc[t][nt][c] = 0.0f;

        #pragma unroll
        for (int tap = 0; tap < 9; tap++) {
            const unsigned toff = (unsigned)(((tap / 3) * 12 + (tap % 3)) * 32);
            unsigned ah[2][4], al[2][4];
            #pragma unroll
            for (int t = 0; t < 2; t++) {
                LDSM4(ah[t][0], ah[t][1], ah[t][2], ah[t][3], ahb[t] + toff);
                LDSM4(al[t][0], al[t][1], al[t][2], al[t][3], alb[t] + toff);
            }
            #pragma unroll
            for (int nt = 0; nt < 4; nt++) {
                const uint2 bh = *(const uint2*)(s_bf_hi + (tap * 4 + nt) * 64 + lane * 2);
                const uint2 bl = *(const uint2*)(s_bf_lo + (tap * 4 + nt) * 64 + lane * 2);
                #pragma unroll
                for (int t = 0; t < 2; t++) {
                    MMA16816(acc[t][nt], ah[t][0], ah[t][1], ah[t][2], ah[t][3], bh.x, bh.y);
                    MMA16816(acc[t][nt], al[t][0], al[t][1], al[t][2], al[t][3], bh.x, bh.y);
                    MMA16816(acc[t][nt], ah[t][0], ah[t][1], ah[t][2], ah[t][3], bl.x, bl.y);
                }
            }
        }
        __syncthreads();   // all act/bf reads done -> C may overwrite them

        // epilogue: fragments -> s_C[p][co], pitch 34 (conflict-free)
        const int col0 = (lane & 3) * 2;
        #pragma unroll
        for (int t = 0; t < 2; t++) {
            const int prow = (wid + t * 13) * 16 + (lane >> 2);
            #pragma unroll
            for (int nt = 0; nt < 4; nt++) {
                const int co0 = nt * 8 + col0;
                *(float2*)&s_C[prow * CPITCH + co0] =
                    make_float2(acc[t][nt][0], acc[t][nt][1]);
                *(float2*)&s_C[(prow + 8) * CPITCH + co0] =
                    make_float2(acc[t][nt][2], acc[t][nt][3]);
            }
        }
    }
    __syncthreads();

    // ---------------- bias + relu + 2x2 maxpool -> s_p2[4][800] --------------------
    for (int o = tid; o < nimg * 800; o += NT) {
        const int im  = o / 800;
        const int oo  = o - im * 800;
        const int co  = oo & 31;
        const int pos = oo >> 5;
        const int r   = pos / 5;
        const int cl  = pos - r * 5;
        const int pb  = im * 100 + (2 * r) * 10 + 2 * cl;
        const float v0 = s_C[(pb     ) * CPITCH + co];
        const float v1 = s_C[(pb +  1) * CPITCH + co];
        const float v2 = s_C[(pb + 10) * CPITCH + co];
        const float v3 = s_C[(pb + 11) * CPITCH + co];
        const float mx = fmaxf(fmaxf(v0, v1), fmaxf(v2, v3)) + s_b2[co];
        s_p2[o] = fmaxf(mx, 0.0f);
    }
    __syncthreads();

    // ---------------- dense 800 -> 4, four images ----------------------------------
    {
        float p[4][4];
        #pragma unroll
        for (int g = 0; g < 4; g++)
            #pragma unroll
            for (int c = 0; c < 4; c++) p[g][c] = 0.0f;

        for (int k = tid; k < 800; k += NT) {
            const float4 w = *(const float4*)(dwg + k * 4);
            #pragma unroll
            for (int g = 0; g < 4; g++) {
                const float v = s_p2[g * 800 + k];
                p[g][0] += v * w.x; p[g][1] += v * w.y;
                p[g][2] += v * w.z; p[g][3] += v * w.w;
            }
        }
        #pragma unroll
        for (int off = 16; off; off >>= 1) {
            #pragma unroll
            for (int g = 0; g < 4; g++)
                #pragma unroll
                for (int c = 0; c < 4; c++)
                    p[g][c] += __shfl_down_sync(0xffffffffu, p[g][c], off);
        }
        if ((tid & 31) == 0) {
            #pragma unroll
            for (int g = 0; g < 4; g++)
                #pragma unroll
                for (int c = 0; c < 4; c++)
                    atomicAdd(&s_feat[g * 4 + c], p[g][c]);
        }
    }
    __syncthreads();

    // ---------------- analytic quantum circuit + sigmoid ---------------------------
    if (tid < 16) {
        const int im = tid >> 2;
        const int j  = tid & 3;
        const int img = img0 + im;
        if (img < B) {
            float pr1[4];
            #pragma unroll
            for (int i = 0; i < 4; i++) {
                const float f = tanhf(s_feat[im * 4 + i]);
                pr1[i] = 0.5f * (1.0f + sinf(f));
            }
            float wj[4];
            #pragma unroll
            for (int i = 0; i < 4; i++) wj[i] = qwg[i * 4 + j];

            float q = 0.0f;
            #pragma unroll
            for (int b = 0; b < 16; b++) {
                float prob = 1.0f, ang = 0.0f;
                #pragma unroll
                for (int i = 0; i < 4; i++) {
                    if (b & (1 << i)) { prob *= pr1[i];        ang += wj[i]; }
                    else              { prob *= 1.0f - pr1[i]; }
                }
                q -= prob * sinf(ang);
            }
            out[img * 4 + j] = 1.0f / (1.0f + expf(-10.0f * q));
        }
    }
}

extern "C" void kernel_launch(void* const* d_in, const int* in_sizes, int n_in,
                              void* d_out, int out_size)
{
    const float* x   = (const float*)d_in[0];
    const float* w1  = (const float*)d_in[1];
    const float* b1  = (const float*)d_in[2];
    const float* w2  = (const float*)d_in[3];
    const float* b2  = (const float*)d_in[4];
    const float* dw  = (const float*)d_in[5];
    const float* db  = (const float*)d_in[6];
    const float* qw  = (const float*)d_in[7];
    float* out = (float*)d_out;

    const int B = in_sizes[0] / 784;   // NHWC 28*28*1
    static bool attr_set = false;
    if (!attr_set) {
        cudaFuncSetAttribute(hybrid_kernel,
                             cudaFuncAttributeMaxDynamicSharedMemorySize, SM_BYTES);
        attr_set = true;
    }
    hybrid_kernel<<<(B + 3) / 4, NT, SM_BYTES>>>(x, w1, b1, w2, b2, dw, db, qw, out, B);
}